// round 7
// baseline (speedup 1.0000x reference)
#include <cuda_runtime.h>
#include <cuda_bf16.h>

// WeightedEmbeddingBag: score[b,m,:] = sum_{n=start_m..end_m-1} emb[input[b,n],:] * psw[b,n]
//   end_m = offsets[b,m]+1, start_m = (m==0) ? 0 : offsets[b,m-1]+1 (offsets sorted)
//
// R7: one warp per bag; explicit 8-row LDG.128 batches (float4 x8 live in regs)
// to maximize outstanding loads per warp. __launch_bounds__(64,16) trades
// occupancy (32 warps/SM) for a ~64-reg budget so the 8 loads stay in flight.
// Padded rows in a batch carry w=0 (and idx=0 -> valid address), so no
// predication in the hot loop.
//
// Inputs: input int32 [B,N], per_sample_weights f32 [B,N],
//         offsets int32 [B,M], emb_weight f32 [VOCAB,D]. Output f32 [B,M,D].

#define BB 4096
#define NN 200
#define MM 26
#define DD 128
#define D4 (DD / 4)   // 32 float4 per row -> one lane each

__global__ __launch_bounds__(64, 16)
void weighted_bag_kernel(const int* __restrict__ input,
                         const float* __restrict__ psw,
                         const int* __restrict__ offsets,
                         const float4* __restrict__ emb4,   // [VOCAB, D4]
                         float4* __restrict__ out4)         // [B, M, D4]
{
    const int gw   = (blockIdx.x * blockDim.x + threadIdx.x) >> 5;
    const int lane = threadIdx.x & 31;
    if (gw >= BB * MM) return;
    const int b = gw / MM;
    const int m = gw - b * MM;

    const int* __restrict__ offs = offsets + b * MM;
    const int end   = __ldg(&offs[m]) + 1;
    const int start = (m == 0) ? 0 : __ldg(&offs[m - 1]) + 1;

    const int*   __restrict__ inp  = input + b * NN;
    const float* __restrict__ wrow = psw   + b * NN;

    float ax = 0.f, ay = 0.f, az = 0.f, aw = 0.f;

    for (int base = start; base < end; base += 32) {
        // coalesced prefetch of up to 32 (index, weight) pairs; pad w=0, idx=0
        const int n_l = base + lane;
        int   my_idx = 0;
        float my_w   = 0.f;
        if (n_l < end) {
            my_idx = __ldg(&inp[n_l]);
            my_w   = __ldg(&wrow[n_l]);
        }
        const int nwin = min(32, end - base);

        for (int g = 0; g < nwin; g += 8) {
            // broadcast 8 (idx, w) pairs (g+j <= 31 always; padded lanes w=0)
            int   idx[8];
            float w[8];
            #pragma unroll
            for (int j = 0; j < 8; ++j) {
                idx[j] = __shfl_sync(0xffffffffu, my_idx, g + j);
                w[j]   = __shfl_sync(0xffffffffu, my_w,   g + j);
            }
            // 8 independent 512B row gathers issued back-to-back
            float4 v[8];
            #pragma unroll
            for (int j = 0; j < 8; ++j)
                v[j] = __ldg(&emb4[(long long)idx[j] * D4 + lane]);
            // consume
            #pragma unroll
            for (int j = 0; j < 8; ++j) {
                ax = fmaf(w[j], v[j].x, ax);
                ay = fmaf(w[j], v[j].y, ay);
                az = fmaf(w[j], v[j].z, az);
                aw = fmaf(w[j], v[j].w, aw);
            }
        }
    }

    float4 o; o.x = ax; o.y = ay; o.z = az; o.w = aw;
    out4[((long long)b * MM + m) * D4 + lane] = o;   // empty bag -> zeros
}

extern "C" void kernel_launch(void* const* d_in, const int* in_sizes, int n_in,
                              void* d_out, int out_size)
{
    const int*    input   = (const int*)   d_in[0];
    const float*  psw     = (const float*) d_in[1];
    const int*    offsets = (const int*)   d_in[2];
    const float4* emb4    = (const float4*)d_in[3];
    float4*       out4    = (float4*)d_out;

    // one warp per (batch, bag): 4096*26 = 106496 warps; 2 warps/block
    const int threads = 64;
    const long long warps = (long long)BB * MM;
    const int blocks = (int)((warps * 32 + threads - 1) / threads);  // 53248
    weighted_bag_kernel<<<blocks, threads>>>(input, psw, offsets, emb4, out4);
}

// round 11
// speedup vs baseline: 1.1052x; 1.1052x over previous
#include <cuda_runtime.h>
#include <cuda_bf16.h>

// WeightedEmbeddingBag: score[b,m,:] = sum_{n=start_m..end_m-1} emb[input[b,n],:] * psw[b,n]
//   end_m = offsets[b,m]+1, start_m = (m==0) ? 0 : offsets[b,m-1]+1 (offsets sorted)
//
// R11: one warp per bag (R5 structure). Cache steering WITHOUT createpolicy
// (two consecutive container failures make the createpolicy asm a suspect):
//   - index/weight/offset loads and the output store use .cs (evict-first
//     streaming) so the ~61MB/launch of streams stops evicting the 51MB
//     embedding table from L2;
//   - table gathers stay plain __ldg (normal LRU priority -> table stays hot).
//
// Inputs: input int32 [B,N], per_sample_weights f32 [B,N],
//         offsets int32 [B,M], emb_weight f32 [VOCAB,D]. Output f32 [B,M,D].

#define BB 4096
#define NN 200
#define MM 26
#define DD 128
#define D4 (DD / 4)   // 32 float4 per row -> one lane each

__global__ __launch_bounds__(256, 8)
void weighted_bag_kernel(const int* __restrict__ input,
                         const float* __restrict__ psw,
                         const int* __restrict__ offsets,
                         const float4* __restrict__ emb4,   // [VOCAB, D4]
                         float4* __restrict__ out4)         // [B, M, D4]
{
    const int gw   = (blockIdx.x * blockDim.x + threadIdx.x) >> 5;
    const int lane = threadIdx.x & 31;
    if (gw >= BB * MM) return;
    const int b = gw / MM;
    const int m = gw - b * MM;

    const int* __restrict__ offs = offsets + b * MM;
    const int end   = __ldcs(&offs[m]) + 1;
    const int start = (m == 0) ? 0 : __ldcs(&offs[m - 1]) + 1;

    const int*   __restrict__ inp  = input + b * NN;
    const float* __restrict__ wrow = psw   + b * NN;

    float ax = 0.f, ay = 0.f, az = 0.f, aw = 0.f;

    for (int base = start; base < end; base += 32) {
        // coalesced streaming prefetch of up to 32 (index, weight) pairs
        const int n_l = base + lane;
        int   my_idx = 0;
        float my_w   = 0.f;
        if (n_l < end) {
            my_idx = __ldcs(&inp[n_l]);
            my_w   = __ldcs(&wrow[n_l]);
        }
        const int cnt = min(32, end - base);

        #pragma unroll 4
        for (int j = 0; j < cnt; ++j) {
            const int   idx = __shfl_sync(0xffffffffu, my_idx, j);
            const float w   = __shfl_sync(0xffffffffu, my_w,   j);

            const float4 v = __ldg(&emb4[(long long)idx * D4 + lane]);  // 512B row gather
            ax = fmaf(w, v.x, ax);
            ay = fmaf(w, v.y, ay);
            az = fmaf(w, v.z, az);
            aw = fmaf(w, v.w, aw);
        }
    }

    float4 o; o.x = ax; o.y = ay; o.z = az; o.w = aw;
    __stcs(&out4[((long long)b * MM + m) * D4 + lane], o);   // streaming store
}

extern "C" void kernel_launch(void* const* d_in, const int* in_sizes, int n_in,
                              void* d_out, int out_size)
{
    const int*    input   = (const int*)   d_in[0];
    const float*  psw     = (const float*) d_in[1];
    const int*    offsets = (const int*)   d_in[2];
    const float4* emb4    = (const float4*)d_in[3];
    float4*       out4    = (float4*)d_out;

    // one warp per (batch, bag): 4096*26 = 106496 warps; 8 warps/block
    const int threads = 256;
    const long long warps = (long long)BB * MM;
    const int blocks = (int)((warps * 32 + threads - 1) / threads);
    weighted_bag_kernel<<<blocks, threads>>>(input, psw, offsets, emb4, out4);
}